// round 9
// baseline (speedup 1.0000x reference)
#include <cuda_runtime.h>
#include <cuda_bf16.h>
#include <cstdint>
#include <math.h>

// ---------------------------------------------------------------------------
// Problem constants (fixed by reference setup_inputs)
// ---------------------------------------------------------------------------
#define N_PTS 4096
#define DIM   256
#define NTOT  8192
#define BM    128
#define NB    (NTOT / BM)            // 64 tile rows
#define NTILES (NB * (NB + 1) / 2)   // 2080 lower-triangle tiles
#define BK    64                     // K chunk (elements)
#define NCHUNK (DIM / BK)            // 4
#define NSTAGE 3                     // smem pipeline stages
#define SSTRIDE 144                  // padded smem row stride: 128B data + 16B pad
#define STAGE_BYTES (128 * SSTRIDE)  // 18432 per matrix per stage
#define SMEM_BUF_OFF 1024
#define SMEM_TOTAL (SMEM_BUF_OFF + 2 * NSTAGE * STAGE_BYTES)  // 111616
#define GRID 296                     // persistent: 2 CTAs per SM on 148 SMs
#define MAXT 8                       // max tiles per CTA (ceil(2080/296))

// Device scratch (no allocation allowed)
__device__ __align__(16) __nv_bfloat16 g_A[NTOT * DIM];  // 4 MB bf16 copy of [X;Y]
__device__ float g_norms[NTOT];
__device__ float g_accum;
__device__ unsigned int g_ticket;

// ---------------------------------------------------------------------------
// PTX helpers (arch-neutral: sm_80+ / sm_75+)
// ---------------------------------------------------------------------------
__device__ __forceinline__ void cpasync16(uint32_t s, const void* g) {
    asm volatile("cp.async.cg.shared.global [%0], [%1], 16;" :: "r"(s), "l"(g));
}

#define LDSM_X4(R, addr) \
    asm volatile("ldmatrix.sync.aligned.m8n8.x4.shared.b16 {%0,%1,%2,%3}, [%4];" \
                 : "=r"((R)[0]), "=r"((R)[1]), "=r"((R)[2]), "=r"((R)[3]) \
                 : "r"(addr))

#define MMA16816(D, A, B) \
    asm volatile("mma.sync.aligned.m16n8k16.row.col.f32.bf16.bf16.f32 " \
                 "{%0,%1,%2,%3}, {%4,%5,%6,%7}, {%8,%9}, {%0,%1,%2,%3};" \
                 : "+f"((D)[0]), "+f"((D)[1]), "+f"((D)[2]), "+f"((D)[3]) \
                 : "r"((A)[0]), "r"((A)[1]), "r"((A)[2]), "r"((A)[3]), \
                   "r"((B)[0]), "r"((B)[1]))

// ---------------------------------------------------------------------------
// Prep: fp32->bf16 conversion + exact fp32 row norms; zero accumulators.
// ---------------------------------------------------------------------------
__global__ void prep_kernel(const float* __restrict__ X,
                            const float* __restrict__ Y) {
    int row  = blockIdx.x * 8 + (threadIdx.x >> 5);
    int lane = threadIdx.x & 31;
    if (blockIdx.x == 0 && threadIdx.x == 0) { g_accum = 0.0f; g_ticket = 0u; }

    const float* p = (row < N_PTS) ? (X + (size_t)row * DIM)
                                   : (Y + (size_t)(row - N_PTS) * DIM);
    float4 v0 = ((const float4*)(p + lane * 8))[0];
    float4 v1 = ((const float4*)(p + lane * 8))[1];

    float s = v0.x * v0.x + v0.y * v0.y + v0.z * v0.z + v0.w * v0.w
            + v1.x * v1.x + v1.y * v1.y + v1.z * v1.z + v1.w * v1.w;
    #pragma unroll
    for (int o = 16; o; o >>= 1) s += __shfl_xor_sync(0xffffffffu, s, o);
    if (lane == 0) g_norms[row] = s;

    __nv_bfloat162 b0 = __floats2bfloat162_rn(v0.x, v0.y);
    __nv_bfloat162 b1 = __floats2bfloat162_rn(v0.z, v0.w);
    __nv_bfloat162 b2 = __floats2bfloat162_rn(v1.x, v1.y);
    __nv_bfloat162 b3 = __floats2bfloat162_rn(v1.z, v1.w);
    uint4 packed;
    packed.x = *(uint32_t*)&b0; packed.y = *(uint32_t*)&b1;
    packed.z = *(uint32_t*)&b2; packed.w = *(uint32_t*)&b3;
    *(uint4*)(g_A + (size_t)row * DIM + lane * 8) = packed;
}

// ---------------------------------------------------------------------------
// Persistent mma.sync kernel: 296 CTAs, each owns tiles bid, bid+296, ...
// The cp.async chunk stream is continuous across tile boundaries: 3-stage
// ring, 2-chunk lookahead, one __syncthreads per chunk. Empty commit_groups
// pad the stream end so "wait_group 2" always means "current chunk landed".
// Per-tile epilogue is register-only (norms via __ldg, weight folded into a
// running per-thread sum); one reduction + atomic per CTA at the very end.
// ---------------------------------------------------------------------------
__global__ __launch_bounds__(256, 2)
void mmd_mma_kernel(float* __restrict__ out) {
    extern __shared__ char smem[];
    float* red = (float*)smem;            // 8-warp final reduction
    const uint32_t sbase =
        (uint32_t)__cvta_generic_to_shared(smem + SMEM_BUF_OFF);

    // Decode this CTA's tile list (lower-triangle index -> row/col origins)
    int cnt = 0;
    int trow[MAXT], tcol[MAXT];
    for (int t = blockIdx.x; t < NTILES; t += GRID) {
        int bi = (int)((sqrtf(8.0f * (float)t + 1.0f) - 1.0f) * 0.5f);
        while ((bi + 1) * (bi + 2) / 2 <= t) bi++;
        while (bi * (bi + 1) / 2 > t)        bi--;
        trow[cnt] = bi * BM;
        tcol[cnt] = (t - bi * (bi + 1) / 2) * BM;
        cnt++;
    }

    const int tid  = threadIdx.x;
    const int wid  = tid >> 5;
    const int lane = tid & 31;
    const int wm = (wid & 3) * 32;   // warp M origin
    const int wn = (wid >> 2) * 64;  // warp N origin
    const uint32_t a_base = (wm + (lane & 15)) * SSTRIDE + ((lane >> 4) * 16);
    const uint32_t b_base = (wn + (lane & 15)) * SSTRIDE + ((lane >> 4) * 16);

    // Continuous chunk stream lookahead
    int la_i = 0, la_c = 0, ring_issue = 0;
    auto issue_next = [&]() {
        if (la_i < cnt) {
            int row0 = trow[la_i], col0 = tcol[la_i];
            uint32_t sa = sbase + (ring_issue % NSTAGE) * 2 * STAGE_BYTES;
            uint32_t sb = sa + STAGE_BYTES;
            #pragma unroll
            for (int it = 0; it < 4; it++) {
                int unit = tid + it * 256;
                int r  = unit >> 3;
                int cs = unit & 7;
                uint32_t soff = r * SSTRIDE + cs * 16;
                const void* ga = g_A + (size_t)(row0 + r) * DIM + la_c * BK + cs * 8;
                const void* gb = g_A + (size_t)(col0 + r) * DIM + la_c * BK + cs * 8;
                cpasync16(sa + soff, ga);
                cpasync16(sb + soff, gb);
            }
        }
        asm volatile("cp.async.commit_group;" ::: "memory");  // may be empty
        ring_issue++;
        if (++la_c == NCHUNK) { la_c = 0; la_i++; }
    };

    float acc[2][8][4];
    #pragma unroll
    for (int mt = 0; mt < 2; mt++)
        #pragma unroll
        for (int nt = 0; nt < 8; nt++)
            #pragma unroll
            for (int r = 0; r < 4; r++) acc[mt][nt][r] = 0.0f;

    float lsum = 0.0f;

    issue_next();  // (tile 0, chunk 0) -> stage 0
    issue_next();  // (tile 0, chunk 1) -> stage 1

    for (int i = 0; i < cnt; i++) {
        const int row0 = trow[i], col0 = tcol[i];

        #pragma unroll
        for (int c = 0; c < NCHUNK; c++) {
            // chunk g = i*4 + c: commits so far = g+2; allow 2 newest pending
            asm volatile("cp.async.wait_group 2;" ::: "memory");
            __syncthreads();
            issue_next();  // chunk g+2 into stage (g+2)%3

            uint32_t sa = sbase + (((unsigned)(i * NCHUNK + c)) % NSTAGE)
                        * 2 * STAGE_BYTES;
            uint32_t sb = sa + STAGE_BYTES;

            #pragma unroll
            for (int s = 0; s < 4; s++) {   // 4 x k16 within the 64-chunk
                uint32_t a_frag[2][4];
                uint32_t b_frag[8][2];
                #pragma unroll
                for (int mt = 0; mt < 2; mt++)
                    LDSM_X4(a_frag[mt], sa + a_base + mt * (16 * SSTRIDE) + s * 32);
                #pragma unroll
                for (int np = 0; np < 4; np++) {
                    uint32_t R[4];
                    LDSM_X4(R, sb + b_base + np * (16 * SSTRIDE) + s * 32);
                    b_frag[np * 2 + 0][0] = R[0]; b_frag[np * 2 + 0][1] = R[2];
                    b_frag[np * 2 + 1][0] = R[1]; b_frag[np * 2 + 1][1] = R[3];
                }
                #pragma unroll
                for (int mt = 0; mt < 2; mt++)
                    #pragma unroll
                    for (int nt = 0; nt < 8; nt++)
                        MMA16816(acc[mt][nt], a_frag[mt], b_frag[nt]);
            }
        }

        // Register-only epilogue; next tile's chunks are already in flight.
        const bool diag = (row0 == col0);
        const float w = ((row0 < N_PTS) ? 1.0f : -1.0f)
                      * ((col0 < N_PTS) ? 1.0f : -1.0f)
                      * (diag ? 1.0f : 2.0f);
        float ni[4];
        #pragma unroll
        for (int mt = 0; mt < 2; mt++)
            #pragma unroll
            for (int rh = 0; rh < 2; rh++)
                ni[mt * 2 + rh] =
                    __ldg(&g_norms[row0 + wm + mt * 16 + (lane >> 2) + rh * 8]);

        float tsum = 0.0f;
        #pragma unroll
        for (int nt = 0; nt < 8; nt++) {
            float nj0 = __ldg(&g_norms[col0 + wn + nt * 8 + (lane & 3) * 2]);
            float nj1 = __ldg(&g_norms[col0 + wn + nt * 8 + (lane & 3) * 2 + 1]);
            #pragma unroll
            for (int mt = 0; mt < 2; mt++) {
                #pragma unroll
                for (int r = 0; r < 4; r++) {
                    float njv = (r & 1) ? nj1 : nj0;
                    float d2 = ni[mt * 2 + (r >> 1)] + njv - 2.0f * acc[mt][nt][r];
                    if (d2 < 40.0f) {  // everything else underflows to 0 in fp32
                        int lrow = wm + mt * 16 + (lane >> 2) + (r >> 1) * 8;
                        int lcol = wn + nt * 8 + (lane & 3) * 2 + (r & 1);
                        if (!(diag && lrow == lcol))
                            tsum += __expf(-0.5f * fmaxf(d2, 0.0f));
                    }
                    acc[mt][nt][r] = 0.0f;  // reset for next tile
                }
            }
        }
        lsum += w * tsum;
    }

    // One reduction + one atomic per CTA
    #pragma unroll
    for (int o = 16; o; o >>= 1) lsum += __shfl_xor_sync(0xffffffffu, lsum, o);
    if (lane == 0) red[wid] = lsum;
    __syncthreads();
    if (tid == 0) {
        float v = 0.0f;
        #pragma unroll
        for (int k = 0; k < 8; k++) v += red[k];
        atomicAdd(&g_accum, v);
        __threadfence();
        unsigned int tk = atomicAdd(&g_ticket, 1u);
        if (tk == GRID - 1) {
            float total = *((volatile float*)&g_accum);
            out[0] = (total + (float)NTOT) * (1.0f / ((float)N_PTS * (float)N_PTS));
        }
    }
}

extern "C" void kernel_launch(void* const* d_in, const int* in_sizes, int n_in,
                              void* d_out, int out_size) {
    const float* X = (const float*)d_in[0];
    const float* Y = (const float*)d_in[1];
    float* out = (float*)d_out;

    cudaFuncSetAttribute(mmd_mma_kernel,
                         cudaFuncAttributeMaxDynamicSharedMemorySize, SMEM_TOTAL);

    prep_kernel<<<NTOT / 8, 256>>>(X, Y);
    mmd_mma_kernel<<<GRID, 256, SMEM_TOTAL>>>(out);
}

// round 10
// speedup vs baseline: 1.0815x; 1.0815x over previous
#include <cuda_runtime.h>
#include <cuda_bf16.h>
#include <cstdint>
#include <math.h>

// ---------------------------------------------------------------------------
// Problem constants (fixed by reference setup_inputs)
// ---------------------------------------------------------------------------
#define N_PTS 4096
#define DIM   256
#define NTOT  8192
#define BM    128
#define NB    (NTOT / BM)            // 64 tile rows
#define NTILES (NB * (NB + 1) / 2)   // 2080 lower-triangle tiles
#define BK    64                     // K chunk (elements)
#define NCHUNK (DIM / BK)            // 4
#define SSTRIDE 144                  // padded smem row stride: 128B data + 16B pad
#define STAGE_BYTES (128 * SSTRIDE)  // 18432 per matrix per stage
#define SMEM_BUF_OFF 2048
#define SMEM_TOTAL (SMEM_BUF_OFF + 4 * STAGE_BYTES)  // 75776

// Device scratch (no allocation allowed)
__device__ __align__(16) __nv_bfloat16 g_A[NTOT * DIM];  // 4 MB bf16 copy of [X;Y]
__device__ float g_norms[NTOT];
__device__ float g_accum;
__device__ unsigned int g_ticket;

// ---------------------------------------------------------------------------
// PTX helpers (arch-neutral: sm_80+ / sm_75+)
// ---------------------------------------------------------------------------
__device__ __forceinline__ void cpasync16(uint32_t s, const void* g) {
    asm volatile("cp.async.cg.shared.global [%0], [%1], 16;" :: "r"(s), "l"(g));
}

#define LDSM_X4(R, addr) \
    asm volatile("ldmatrix.sync.aligned.m8n8.x4.shared.b16 {%0,%1,%2,%3}, [%4];" \
                 : "=r"((R)[0]), "=r"((R)[1]), "=r"((R)[2]), "=r"((R)[3]) \
                 : "r"(addr))

#define MMA16816(D, A, B0, B1) \
    asm volatile("mma.sync.aligned.m16n8k16.row.col.f32.bf16.bf16.f32 " \
                 "{%0,%1,%2,%3}, {%4,%5,%6,%7}, {%8,%9}, {%0,%1,%2,%3};" \
                 : "+f"((D)[0]), "+f"((D)[1]), "+f"((D)[2]), "+f"((D)[3]) \
                 : "r"((A)[0]), "r"((A)[1]), "r"((A)[2]), "r"((A)[3]), \
                   "r"(B0), "r"(B1))

// ---------------------------------------------------------------------------
// Prep: fp32->bf16 conversion + exact fp32 row norms; zero accumulators.
// ---------------------------------------------------------------------------
__global__ void prep_kernel(const float* __restrict__ X,
                            const float* __restrict__ Y) {
    int row  = blockIdx.x * 8 + (threadIdx.x >> 5);
    int lane = threadIdx.x & 31;
    if (blockIdx.x == 0 && threadIdx.x == 0) { g_accum = 0.0f; g_ticket = 0u; }

    const float* p = (row < N_PTS) ? (X + (size_t)row * DIM)
                                   : (Y + (size_t)(row - N_PTS) * DIM);
    float4 v0 = ((const float4*)(p + lane * 8))[0];
    float4 v1 = ((const float4*)(p + lane * 8))[1];

    float s = v0.x * v0.x + v0.y * v0.y + v0.z * v0.z + v0.w * v0.w
            + v1.x * v1.x + v1.y * v1.y + v1.z * v1.z + v1.w * v1.w;
    #pragma unroll
    for (int o = 16; o; o >>= 1) s += __shfl_xor_sync(0xffffffffu, s, o);
    if (lane == 0) g_norms[row] = s;

    __nv_bfloat162 b0 = __floats2bfloat162_rn(v0.x, v0.y);
    __nv_bfloat162 b1 = __floats2bfloat162_rn(v0.z, v0.w);
    __nv_bfloat162 b2 = __floats2bfloat162_rn(v1.x, v1.y);
    __nv_bfloat162 b3 = __floats2bfloat162_rn(v1.z, v1.w);
    uint4 packed;
    packed.x = *(uint32_t*)&b0; packed.y = *(uint32_t*)&b1;
    packed.z = *(uint32_t*)&b2; packed.w = *(uint32_t*)&b3;
    *(uint4*)(g_A + (size_t)row * DIM + lane * 8) = packed;
}

// ---------------------------------------------------------------------------
// Main mma.sync tile kernel (round-6 base + register fragment double-buffer):
// one 128x128 lower-triangle tile per CTA; 256 threads = 8 warps (4x2);
// warp tile 32x64; double-buffered cp.async over 4 K-chunks of 64.
// Inside each chunk the s-loop preloads fragments for s+1 while issuing
// MMAs on s, hiding LDS latency behind tensor work.
// ---------------------------------------------------------------------------
__global__ __launch_bounds__(256, 2)
void mmd_mma_kernel(float* __restrict__ out) {
    extern __shared__ char smem[];
    float* srm = (float*)smem;            // 128 row norms
    float* srn = (float*)(smem + 512);    // 128 col norms
    float* red = (float*)(smem + 1024);   // 8-warp reduction
    const uint32_t sbase =
        (uint32_t)__cvta_generic_to_shared(smem + SMEM_BUF_OFF);

    // Decode lower-triangle tile index -> (bi, bj), bi >= bj
    int t  = blockIdx.x;
    int bi = (int)((sqrtf(8.0f * (float)t + 1.0f) - 1.0f) * 0.5f);
    while ((bi + 1) * (bi + 2) / 2 <= t) bi++;
    while (bi * (bi + 1) / 2 > t)        bi--;
    int bj = t - bi * (bi + 1) / 2;

    const int tid  = threadIdx.x;
    const int wid  = tid >> 5;
    const int lane = tid & 31;
    const int row0 = bi * BM;
    const int col0 = bj * BM;

    if (tid < 128) srm[tid] = g_norms[row0 + tid];
    else           srn[tid - 128] = g_norms[col0 + tid - 128];

    // cp.async issue of one K-chunk (64 elems = 128B/row) into stage st
    auto issue = [&](int c, int st) {
        uint32_t sa = sbase + st * 2 * STAGE_BYTES;
        uint32_t sb = sa + STAGE_BYTES;
        #pragma unroll
        for (int it = 0; it < 4; it++) {
            int unit = tid + it * 256;
            int r  = unit >> 3;
            int cs = unit & 7;
            uint32_t soff = r * SSTRIDE + cs * 16;
            const void* ga = g_A + (size_t)(row0 + r) * DIM + c * BK + cs * 8;
            const void* gb = g_A + (size_t)(col0 + r) * DIM + c * BK + cs * 8;
            cpasync16(sa + soff, ga);
            cpasync16(sb + soff, gb);
        }
        asm volatile("cp.async.commit_group;" ::: "memory");
    };

    float acc[2][8][4];
    #pragma unroll
    for (int mt = 0; mt < 2; mt++)
        #pragma unroll
        for (int nt = 0; nt < 8; nt++)
            #pragma unroll
            for (int r = 0; r < 4; r++) acc[mt][nt][r] = 0.0f;

    const int wm = (wid & 3) * 32;   // warp M origin
    const int wn = (wid >> 2) * 64;  // warp N origin

    // Hoisted per-thread ldmatrix base offsets (stage-relative)
    const uint32_t a_base = (wm + (lane & 15)) * SSTRIDE + ((lane >> 4) * 16);
    const uint32_t b_base = (wn + (lane & 15)) * SSTRIDE + ((lane >> 4) * 16);

    issue(0, 0);

    for (int c = 0; c < NCHUNK; c++) {
        int st = c & 1;
        if (c + 1 < NCHUNK) {
            issue(c + 1, st ^ 1);
            asm volatile("cp.async.wait_group 1;" ::: "memory");
        } else {
            asm volatile("cp.async.wait_group 0;" ::: "memory");
        }
        __syncthreads();

        uint32_t sa = sbase + st * 2 * STAGE_BYTES;
        uint32_t sb = sa + STAGE_BYTES;

        // Fragment double-buffer: preload s=0; in iter s, load s+1 into the
        // alternate buffer before issuing MMAs on the current one.
        uint32_t a_frag[2][2][4];   // [buf][mt][4]
        uint32_t b_reg[2][4][4];    // [buf][np][4]

        #pragma unroll
        for (int mt = 0; mt < 2; mt++)
            LDSM_X4(a_frag[0][mt], sa + a_base + mt * (16 * SSTRIDE));
        #pragma unroll
        for (int np = 0; np < 4; np++)
            LDSM_X4(b_reg[0][np], sb + b_base + np * (16 * SSTRIDE));

        #pragma unroll
        for (int s = 0; s < 4; s++) {       // 4 x k16 within the 64-chunk
            const int cur = s & 1, nxt = cur ^ 1;
            if (s < 3) {
                #pragma unroll
                for (int mt = 0; mt < 2; mt++)
                    LDSM_X4(a_frag[nxt][mt],
                            sa + a_base + mt * (16 * SSTRIDE) + (s + 1) * 32);
                #pragma unroll
                for (int np = 0; np < 4; np++)
                    LDSM_X4(b_reg[nxt][np],
                            sb + b_base + np * (16 * SSTRIDE) + (s + 1) * 32);
            }
            #pragma unroll
            for (int mt = 0; mt < 2; mt++) {
                #pragma unroll
                for (int np = 0; np < 4; np++) {
                    MMA16816(acc[mt][np * 2 + 0], a_frag[cur][mt],
                             b_reg[cur][np][0], b_reg[cur][np][2]);
                    MMA16816(acc[mt][np * 2 + 1], a_frag[cur][mt],
                             b_reg[cur][np][1], b_reg[cur][np][3]);
                }
            }
        }
        __syncthreads();
    }

    // Epilogue
    const bool diag = (bi == bj);
    const float w = ((row0 < N_PTS) ? 1.0f : -1.0f)
                  * ((col0 < N_PTS) ? 1.0f : -1.0f)
                  * (diag ? 1.0f : 2.0f);
    float local = 0.0f;
    #pragma unroll
    for (int mt = 0; mt < 2; mt++) {
        #pragma unroll
        for (int nt = 0; nt < 8; nt++) {
            #pragma unroll
            for (int r = 0; r < 4; r++) {
                int lrow = wm + mt * 16 + (lane >> 2) + (r >> 1) * 8;
                int lcol = wn + nt * 8 + (lane & 3) * 2 + (r & 1);
                float d2 = srm[lrow] + srn[lcol] - 2.0f * acc[mt][nt][r];
                if (d2 < 40.0f) {  // everything else underflows to 0 in fp32
                    if (!(diag && lrow == lcol))
                        local += __expf(-0.5f * fmaxf(d2, 0.0f));
                }
            }
        }
    }

    #pragma unroll
    for (int o = 16; o; o >>= 1) local += __shfl_xor_sync(0xffffffffu, local, o);
    if (lane == 0) red[wid] = local;
    __syncthreads();
    if (tid == 0) {
        float v = 0.0f;
        #pragma unroll
        for (int i = 0; i < 8; i++) v += red[i];
        atomicAdd(&g_accum, w * v);
        __threadfence();
        unsigned int tk = atomicAdd(&g_ticket, 1u);
        if (tk == NTILES - 1) {
            float total = *((volatile float*)&g_accum);
            out[0] = (total + (float)NTOT) * (1.0f / ((float)N_PTS * (float)N_PTS));
        }
    }
}

extern "C" void kernel_launch(void* const* d_in, const int* in_sizes, int n_in,
                              void* d_out, int out_size) {
    const float* X = (const float*)d_in[0];
    const float* Y = (const float*)d_in[1];
    float* out = (float*)d_out;

    cudaFuncSetAttribute(mmd_mma_kernel,
                         cudaFuncAttributeMaxDynamicSharedMemorySize, SMEM_TOTAL);

    prep_kernel<<<NTOT / 8, 256>>>(X, Y);
    mmd_mma_kernel<<<NTILES, 256, SMEM_TOTAL>>>(out);
}

// round 11
// speedup vs baseline: 1.1824x; 1.0932x over previous
#include <cuda_runtime.h>
#include <cuda_bf16.h>
#include <cstdint>
#include <math.h>

// ---------------------------------------------------------------------------
// Problem constants (fixed by reference setup_inputs)
// ---------------------------------------------------------------------------
#define N_PTS 4096
#define DIM   256
#define NTOT  8192
#define BM    128
#define NB    (NTOT / BM)            // 64 tile rows
#define NTILES (NB * (NB + 1) / 2)   // 2080 lower-triangle tiles
#define BK    64                     // K chunk (elements)
#define NCHUNK (DIM / BK)            // 4
#define SSTRIDE 144                  // padded smem row stride: 128B data + 16B pad
#define STAGE_BYTES (128 * SSTRIDE)  // 18432 per matrix per stage
#define SMEM_BUF_OFF 2048
#define SMEM_TOTAL (SMEM_BUF_OFF + 4 * STAGE_BYTES)  // 75776

// Device scratch (no allocation allowed)
__device__ __align__(16) __nv_bfloat16 g_A[NTOT * DIM];  // 4 MB bf16 copy of [X;Y]
__device__ float g_norms[NTOT];
__device__ float g_accum;
__device__ unsigned int g_ticket;

// ---------------------------------------------------------------------------
// PTX helpers (arch-neutral: sm_80+ / sm_75+)
// ---------------------------------------------------------------------------
__device__ __forceinline__ void cpasync16(uint32_t s, const void* g) {
    asm volatile("cp.async.cg.shared.global [%0], [%1], 16;" :: "r"(s), "l"(g));
}

#define LDSM_X4(R, addr) \
    asm volatile("ldmatrix.sync.aligned.m8n8.x4.shared.b16 {%0,%1,%2,%3}, [%4];" \
                 : "=r"((R)[0]), "=r"((R)[1]), "=r"((R)[2]), "=r"((R)[3]) \
                 : "r"(addr))

#define MMA16816(D, A, B0, B1) \
    asm volatile("mma.sync.aligned.m16n8k16.row.col.f32.bf16.bf16.f32 " \
                 "{%0,%1,%2,%3}, {%4,%5,%6,%7}, {%8,%9}, {%0,%1,%2,%3};" \
                 : "+f"((D)[0]), "+f"((D)[1]), "+f"((D)[2]), "+f"((D)[3]) \
                 : "r"((A)[0]), "r"((A)[1]), "r"((A)[2]), "r"((A)[3]), \
                   "r"(B0), "r"(B1))

// ---------------------------------------------------------------------------
// Prep: fp32->bf16 conversion + exact fp32 row norms; zero accumulators.
// ---------------------------------------------------------------------------
__global__ void prep_kernel(const float* __restrict__ X,
                            const float* __restrict__ Y) {
    int row  = blockIdx.x * 8 + (threadIdx.x >> 5);
    int lane = threadIdx.x & 31;
    if (blockIdx.x == 0 && threadIdx.x == 0) { g_accum = 0.0f; g_ticket = 0u; }

    const float* p = (row < N_PTS) ? (X + (size_t)row * DIM)
                                   : (Y + (size_t)(row - N_PTS) * DIM);
    float4 v0 = ((const float4*)(p + lane * 8))[0];
    float4 v1 = ((const float4*)(p + lane * 8))[1];

    float s = v0.x * v0.x + v0.y * v0.y + v0.z * v0.z + v0.w * v0.w
            + v1.x * v1.x + v1.y * v1.y + v1.z * v1.z + v1.w * v1.w;
    #pragma unroll
    for (int o = 16; o; o >>= 1) s += __shfl_xor_sync(0xffffffffu, s, o);
    if (lane == 0) g_norms[row] = s;

    __nv_bfloat162 b0 = __floats2bfloat162_rn(v0.x, v0.y);
    __nv_bfloat162 b1 = __floats2bfloat162_rn(v0.z, v0.w);
    __nv_bfloat162 b2 = __floats2bfloat162_rn(v1.x, v1.y);
    __nv_bfloat162 b3 = __floats2bfloat162_rn(v1.z, v1.w);
    uint4 packed;
    packed.x = *(uint32_t*)&b0; packed.y = *(uint32_t*)&b1;
    packed.z = *(uint32_t*)&b2; packed.w = *(uint32_t*)&b3;
    *(uint4*)(g_A + (size_t)row * DIM + lane * 8) = packed;
}

// ---------------------------------------------------------------------------
// Main mma.sync tile kernel (round-6 mainloop, group-skip epilogue):
// one 128x128 lower-triangle tile per CTA; 256 threads = 8 warps (4x2);
// warp tile 32x64; double-buffered cp.async over 4 K-chunks of 64.
// Epilogue tests each 4-acc fragment with one conservative bound
// (2*max(acc) > min(ni)+min(nj)-40); only hits run the scalar exp loop.
// Semantics match the per-element d^2<40 underflow threshold.
// ---------------------------------------------------------------------------
__global__ __launch_bounds__(256, 2)
void mmd_mma_kernel(float* __restrict__ out) {
    extern __shared__ char smem[];
    float* srm = (float*)smem;            // 128 row norms
    float* srn = (float*)(smem + 512);    // 128 col norms
    float* red = (float*)(smem + 1024);   // 8-warp reduction
    const uint32_t sbase =
        (uint32_t)__cvta_generic_to_shared(smem + SMEM_BUF_OFF);

    // Decode lower-triangle tile index -> (bi, bj), bi >= bj
    int t  = blockIdx.x;
    int bi = (int)((sqrtf(8.0f * (float)t + 1.0f) - 1.0f) * 0.5f);
    while ((bi + 1) * (bi + 2) / 2 <= t) bi++;
    while (bi * (bi + 1) / 2 > t)        bi--;
    int bj = t - bi * (bi + 1) / 2;

    const int tid  = threadIdx.x;
    const int wid  = tid >> 5;
    const int lane = tid & 31;
    const int row0 = bi * BM;
    const int col0 = bj * BM;

    if (tid < 128) srm[tid] = g_norms[row0 + tid];
    else           srn[tid - 128] = g_norms[col0 + tid - 128];

    // cp.async issue of one K-chunk (64 elems = 128B/row) into stage st
    auto issue = [&](int c, int st) {
        uint32_t sa = sbase + st * 2 * STAGE_BYTES;
        uint32_t sb = sa + STAGE_BYTES;
        #pragma unroll
        for (int it = 0; it < 4; it++) {
            int unit = tid + it * 256;
            int r  = unit >> 3;
            int cs = unit & 7;
            uint32_t soff = r * SSTRIDE + cs * 16;
            const void* ga = g_A + (size_t)(row0 + r) * DIM + c * BK + cs * 8;
            const void* gb = g_A + (size_t)(col0 + r) * DIM + c * BK + cs * 8;
            cpasync16(sa + soff, ga);
            cpasync16(sb + soff, gb);
        }
        asm volatile("cp.async.commit_group;" ::: "memory");
    };

    float acc[2][8][4];
    #pragma unroll
    for (int mt = 0; mt < 2; mt++)
        #pragma unroll
        for (int nt = 0; nt < 8; nt++)
            #pragma unroll
            for (int r = 0; r < 4; r++) acc[mt][nt][r] = 0.0f;

    const int wm = (wid & 3) * 32;   // warp M origin
    const int wn = (wid >> 2) * 64;  // warp N origin

    // Hoisted per-thread ldmatrix base offsets (stage-relative)
    const uint32_t a_base = (wm + (lane & 15)) * SSTRIDE + ((lane >> 4) * 16);
    const uint32_t b_base = (wn + (lane & 15)) * SSTRIDE + ((lane >> 4) * 16);

    issue(0, 0);

    #pragma unroll
    for (int c = 0; c < NCHUNK; c++) {
        int st = c & 1;
        if (c + 1 < NCHUNK) {
            issue(c + 1, st ^ 1);
            asm volatile("cp.async.wait_group 1;" ::: "memory");
        } else {
            asm volatile("cp.async.wait_group 0;" ::: "memory");
        }
        __syncthreads();

        uint32_t sa = sbase + st * 2 * STAGE_BYTES;
        uint32_t sb = sa + STAGE_BYTES;

        #pragma unroll
        for (int s = 0; s < 4; s++) {       // 4 x k16 within the 64-chunk
            uint32_t a_frag[2][4];
            uint32_t b_reg[4][4];
            #pragma unroll
            for (int mt = 0; mt < 2; mt++)
                LDSM_X4(a_frag[mt], sa + a_base + mt * (16 * SSTRIDE) + s * 32);
            #pragma unroll
            for (int np = 0; np < 4; np++)
                LDSM_X4(b_reg[np], sb + b_base + np * (16 * SSTRIDE) + s * 32);
            #pragma unroll
            for (int mt = 0; mt < 2; mt++) {
                #pragma unroll
                for (int np = 0; np < 4; np++) {
                    MMA16816(acc[mt][np * 2 + 0], a_frag[mt],
                             b_reg[np][0], b_reg[np][2]);
                    MMA16816(acc[mt][np * 2 + 1], a_frag[mt],
                             b_reg[np][1], b_reg[np][3]);
                }
            }
        }
        __syncthreads();
    }

    // ---- Group-skip epilogue ----
    const bool diag = (bi == bj);
    const float w = ((row0 < N_PTS) ? 1.0f : -1.0f)
                  * ((col0 < N_PTS) ? 1.0f : -1.0f)
                  * (diag ? 1.0f : 2.0f);

    float ni0[2], ni1[2], nim[2];
    #pragma unroll
    for (int mt = 0; mt < 2; mt++) {
        ni0[mt] = srm[wm + mt * 16 + (lane >> 2)];
        ni1[mt] = srm[wm + mt * 16 + (lane >> 2) + 8];
        nim[mt] = fminf(ni0[mt], ni1[mt]);
    }

    float local = 0.0f;
    #pragma unroll
    for (int nt = 0; nt < 8; nt++) {
        const int jc = wn + nt * 8 + (lane & 3) * 2;
        const float nj0 = srn[jc];
        const float nj1 = srn[jc + 1];
        const float njm = fminf(nj0, nj1);
        #pragma unroll
        for (int mt = 0; mt < 2; mt++) {
            const float* a = acc[mt][nt];
            float gmax = fmaxf(fmaxf(a[0], a[1]), fmaxf(a[2], a[3]));
            // Any elem with d2 < 40  =>  2*g > ni+nj-40 >= nim+njm-40
            if (2.0f * gmax > nim[mt] + njm - 40.0f) {
                #pragma unroll
                for (int r = 0; r < 4; r++) {
                    float niv = (r >> 1) ? ni1[mt] : ni0[mt];
                    float njv = (r & 1) ? nj1 : nj0;
                    float d2 = niv + njv - 2.0f * a[r];
                    if (d2 < 40.0f) {
                        int lrow = wm + mt * 16 + (lane >> 2) + (r >> 1) * 8;
                        int lcol = jc + (r & 1);
                        if (!(diag && lrow == lcol))
                            local += __expf(-0.5f * fmaxf(d2, 0.0f));
                    }
                }
            }
        }
    }

    #pragma unroll
    for (int o = 16; o; o >>= 1) local += __shfl_xor_sync(0xffffffffu, local, o);
    if (lane == 0) red[wid] = local;
    __syncthreads();
    if (tid == 0) {
        float v = 0.0f;
        #pragma unroll
        for (int i = 0; i < 8; i++) v += red[i];
        atomicAdd(&g_accum, w * v);
        __threadfence();
        unsigned int tk = atomicAdd(&g_ticket, 1u);
        if (tk == NTILES - 1) {
            float total = *((volatile float*)&g_accum);
            out[0] = (total + (float)NTOT) * (1.0f / ((float)N_PTS * (float)N_PTS));
        }
    }
}

extern "C" void kernel_launch(void* const* d_in, const int* in_sizes, int n_in,
                              void* d_out, int out_size) {
    const float* X = (const float*)d_in[0];
    const float* Y = (const float*)d_in[1];
    float* out = (float*)d_out;

    cudaFuncSetAttribute(mmd_mma_kernel,
                         cudaFuncAttributeMaxDynamicSharedMemorySize, SMEM_TOTAL);

    prep_kernel<<<NTOT / 8, 256>>>(X, Y);
    mmd_mma_kernel<<<NTILES, 256, SMEM_TOTAL>>>(out);
}

// round 12
// speedup vs baseline: 1.2211x; 1.0327x over previous
#include <cuda_runtime.h>
#include <cuda_bf16.h>
#include <cstdint>
#include <math.h>

// ---------------------------------------------------------------------------
// Problem constants (fixed by reference setup_inputs)
// ---------------------------------------------------------------------------
#define N_PTS 4096
#define DIM   256
#define NTOT  8192
#define BM    128
#define NB    (NTOT / BM)            // 64 tile rows
#define NTILES (NB * (NB + 1) / 2)   // 2080 lower-triangle tiles
#define NFULL 2072                   // 7 * 296 full-tile CTAs
#define NTAILT (NTILES - NFULL)      // 8 tiles split into strips
#define NSTRIP (NTAILT * 4)          // 32 strip CTAs (128x32 each)
#define GRIDT (NFULL + NSTRIP)       // 2104
#define BK    64                     // K chunk (elements)
#define NCHUNK (DIM / BK)            // 4
#define SSTRIDE 144                  // padded smem row stride: 128B data + 16B pad
#define STAGE_BYTES (128 * SSTRIDE)  // 18432 per matrix per stage
#define SMEM_BUF_OFF 2048
#define SMEM_TOTAL (SMEM_BUF_OFF + 4 * STAGE_BYTES)  // 75776

// Device scratch (no allocation allowed)
__device__ __align__(16) __nv_bfloat16 g_A[NTOT * DIM];  // 4 MB bf16 copy of [X;Y]
__device__ float g_norms[NTOT];
__device__ float g_accum;
__device__ unsigned int g_ticket;

// ---------------------------------------------------------------------------
// PTX helpers (arch-neutral: sm_80+ / sm_75+)
// ---------------------------------------------------------------------------
__device__ __forceinline__ void cpasync16(uint32_t s, const void* g) {
    asm volatile("cp.async.cg.shared.global [%0], [%1], 16;" :: "r"(s), "l"(g));
}

#define LDSM_X4(R, addr) \
    asm volatile("ldmatrix.sync.aligned.m8n8.x4.shared.b16 {%0,%1,%2,%3}, [%4];" \
                 : "=r"((R)[0]), "=r"((R)[1]), "=r"((R)[2]), "=r"((R)[3]) \
                 : "r"(addr))

#define MMA16816(D, A, B0, B1) \
    asm volatile("mma.sync.aligned.m16n8k16.row.col.f32.bf16.bf16.f32 " \
                 "{%0,%1,%2,%3}, {%4,%5,%6,%7}, {%8,%9}, {%0,%1,%2,%3};" \
                 : "+f"((D)[0]), "+f"((D)[1]), "+f"((D)[2]), "+f"((D)[3]) \
                 : "r"((A)[0]), "r"((A)[1]), "r"((A)[2]), "r"((A)[3]), \
                   "r"(B0), "r"(B1))

// ---------------------------------------------------------------------------
// Prep: fp32->bf16 conversion + exact fp32 row norms; zero accumulators.
// Warp handles 4 rows; each thread issues 8 independent float4 loads (MLP=8).
// ---------------------------------------------------------------------------
__global__ void prep_kernel(const float* __restrict__ X,
                            const float* __restrict__ Y) {
    const int wid  = threadIdx.x >> 5;
    const int lane = threadIdx.x & 31;
    const int row  = blockIdx.x * 32 + wid * 4 + (lane >> 3);
    const int seg  = lane & 7;   // float4 segment within the row group
    if (blockIdx.x == 0 && threadIdx.x == 0) { g_accum = 0.0f; g_ticket = 0u; }

    const float* p = (row < N_PTS) ? (X + (size_t)row * DIM)
                                   : (Y + (size_t)(row - N_PTS) * DIM);
    const float4* p4 = (const float4*)p;
    float4 v[8];
    #pragma unroll
    for (int i = 0; i < 8; i++) v[i] = p4[seg + i * 8];

    float s = 0.0f;
    #pragma unroll
    for (int i = 0; i < 8; i++)
        s += v[i].x * v[i].x + v[i].y * v[i].y
           + v[i].z * v[i].z + v[i].w * v[i].w;
    #pragma unroll
    for (int o = 4; o; o >>= 1) s += __shfl_xor_sync(0xffffffffu, s, o);
    if ((lane & 7) == 0) g_norms[row] = s;

    #pragma unroll
    for (int i = 0; i < 8; i++) {
        __nv_bfloat162 b0 = __floats2bfloat162_rn(v[i].x, v[i].y);
        __nv_bfloat162 b1 = __floats2bfloat162_rn(v[i].z, v[i].w);
        uint2 pk;
        pk.x = *(uint32_t*)&b0; pk.y = *(uint32_t*)&b1;
        *(uint2*)(g_A + (size_t)row * DIM + (seg + i * 8) * 4) = pk;
    }
}

// ---------------------------------------------------------------------------
// Main mma.sync kernel.
// CTAs [0, NFULL): one 128x128 lower-triangle tile each (round-11 path).
// CTAs [NFULL, GRIDT): 128x32 column strips of the last 8 tiles — launched
// last so the 8th scheduling round is ~0.4 tile-times on 32 slots instead of
// a full tile-time on 8 slots (kills the wave-quantization tail).
// ---------------------------------------------------------------------------
__global__ __launch_bounds__(256, 2)
void mmd_mma_kernel(float* __restrict__ out) {
    extern __shared__ char smem[];
    float* srm = (float*)smem;            // 128 row norms
    float* srn = (float*)(smem + 512);    // 128 col norms
    float* red = (float*)(smem + 1024);   // 8-warp reduction
    const uint32_t sbase =
        (uint32_t)__cvta_generic_to_shared(smem + SMEM_BUF_OFF);

    const int tid  = threadIdx.x;
    const int wid  = tid >> 5;
    const int lane = tid & 31;

    float local = 0.0f;   // per-thread weighted sum
    float wgt   = 1.0f;

    if (blockIdx.x < NFULL) {
        // ================= FULL 128x128 TILE PATH =================
        int t  = blockIdx.x;
        int bi = (int)((sqrtf(8.0f * (float)t + 1.0f) - 1.0f) * 0.5f);
        while ((bi + 1) * (bi + 2) / 2 <= t) bi++;
        while (bi * (bi + 1) / 2 > t)        bi--;
        int bj = t - bi * (bi + 1) / 2;
        const int row0 = bi * BM;
        const int col0 = bj * BM;

        if (tid < 128) srm[tid] = g_norms[row0 + tid];
        else           srn[tid - 128] = g_norms[col0 + tid - 128];

        auto issue = [&](int c, int st) {
            uint32_t sa = sbase + st * 2 * STAGE_BYTES;
            uint32_t sb = sa + STAGE_BYTES;
            #pragma unroll
            for (int it = 0; it < 4; it++) {
                int unit = tid + it * 256;
                int r  = unit >> 3;
                int cs = unit & 7;
                uint32_t soff = r * SSTRIDE + cs * 16;
                const void* ga = g_A + (size_t)(row0 + r) * DIM + c * BK + cs * 8;
                const void* gb = g_A + (size_t)(col0 + r) * DIM + c * BK + cs * 8;
                cpasync16(sa + soff, ga);
                cpasync16(sb + soff, gb);
            }
            asm volatile("cp.async.commit_group;" ::: "memory");
        };

        float acc[2][8][4];
        #pragma unroll
        for (int mt = 0; mt < 2; mt++)
            #pragma unroll
            for (int nt = 0; nt < 8; nt++)
                #pragma unroll
                for (int r = 0; r < 4; r++) acc[mt][nt][r] = 0.0f;

        const int wm = (wid & 3) * 32;
        const int wn = (wid >> 2) * 64;
        const uint32_t a_base = (wm + (lane & 15)) * SSTRIDE + ((lane >> 4) * 16);
        const uint32_t b_base = (wn + (lane & 15)) * SSTRIDE + ((lane >> 4) * 16);

        issue(0, 0);

        #pragma unroll
        for (int c = 0; c < NCHUNK; c++) {
            int st = c & 1;
            if (c + 1 < NCHUNK) {
                issue(c + 1, st ^ 1);
                asm volatile("cp.async.wait_group 1;" ::: "memory");
            } else {
                asm volatile("cp.async.wait_group 0;" ::: "memory");
            }
            __syncthreads();

            uint32_t sa = sbase + st * 2 * STAGE_BYTES;
            uint32_t sb = sa + STAGE_BYTES;

            #pragma unroll
            for (int s = 0; s < 4; s++) {
                uint32_t a_frag[2][4];
                uint32_t b_reg[4][4];
                #pragma unroll
                for (int mt = 0; mt < 2; mt++)
                    LDSM_X4(a_frag[mt], sa + a_base + mt * (16 * SSTRIDE) + s * 32);
                #pragma unroll
                for (int np = 0; np < 4; np++)
                    LDSM_X4(b_reg[np], sb + b_base + np * (16 * SSTRIDE) + s * 32);
                #pragma unroll
                for (int mt = 0; mt < 2; mt++) {
                    #pragma unroll
                    for (int np = 0; np < 4; np++) {
                        MMA16816(acc[mt][np * 2 + 0], a_frag[mt],
                                 b_reg[np][0], b_reg[np][2]);
                        MMA16816(acc[mt][np * 2 + 1], a_frag[mt],
                                 b_reg[np][1], b_reg[np][3]);
                    }
                }
            }
            __syncthreads();
        }

        // Group-skip epilogue
        const bool diag = (bi == bj);
        wgt = ((row0 < N_PTS) ? 1.0f : -1.0f)
            * ((col0 < N_PTS) ? 1.0f : -1.0f)
            * (diag ? 1.0f : 2.0f);

        float ni0[2], ni1[2], nim[2];
        #pragma unroll
        for (int mt = 0; mt < 2; mt++) {
            ni0[mt] = srm[wm + mt * 16 + (lane >> 2)];
            ni1[mt] = srm[wm + mt * 16 + (lane >> 2) + 8];
            nim[mt] = fminf(ni0[mt], ni1[mt]);
        }
        #pragma unroll
        for (int nt = 0; nt < 8; nt++) {
            const int jc = wn + nt * 8 + (lane & 3) * 2;
            const float nj0 = srn[jc];
            const float nj1 = srn[jc + 1];
            const float njm = fminf(nj0, nj1);
            #pragma unroll
            for (int mt = 0; mt < 2; mt++) {
                const float* a = acc[mt][nt];
                float gmax = fmaxf(fmaxf(a[0], a[1]), fmaxf(a[2], a[3]));
                if (2.0f * gmax > nim[mt] + njm - 40.0f) {
                    #pragma unroll
                    for (int r = 0; r < 4; r++) {
                        float niv = (r >> 1) ? ni1[mt] : ni0[mt];
                        float njv = (r & 1) ? nj1 : nj0;
                        float d2 = niv + njv - 2.0f * a[r];
                        if (d2 < 40.0f) {
                            int lrow = wm + mt * 16 + (lane >> 2) + (r >> 1) * 8;
                            int lcol = jc + (r & 1);
                            if (!(diag && lrow == lcol))
                                local += __expf(-0.5f * fmaxf(d2, 0.0f));
                        }
                    }
                }
            }
        }
    } else {
        // ================= 128x32 STRIP PATH (last 8 tiles) =================
        int q  = blockIdx.x - NFULL;          // 0..31
        int t  = NFULL + (q >> 2);            // 2072..2079
        int bi = (int)((sqrtf(8.0f * (float)t + 1.0f) - 1.0f) * 0.5f);
        while ((bi + 1) * (bi + 2) / 2 <= t) bi++;
        while (bi * (bi + 1) / 2 > t)        bi--;
        int bj = t - bi * (bi + 1) / 2;
        const int row0  = bi * BM;
        const int colT  = bj * BM;                 // parent tile col origin
        const int col0  = colT + (q & 3) * 32;     // strip col origin

        if (tid < 128)       srm[tid] = g_norms[row0 + tid];
        else if (tid < 160)  srn[tid - 128] = g_norms[col0 + tid - 128];

        auto issue_s = [&](int c, int st) {
            uint32_t sa = sbase + st * 2 * STAGE_BYTES;
            uint32_t sb = sa + STAGE_BYTES;
            #pragma unroll
            for (int it = 0; it < 4; it++) {   // A: 128 rows
                int unit = tid + it * 256;
                int r  = unit >> 3;
                int cs = unit & 7;
                uint32_t soff = r * SSTRIDE + cs * 16;
                const void* ga = g_A + (size_t)(row0 + r) * DIM + c * BK + cs * 8;
                cpasync16(sa + soff, ga);
            }
            {   // B: 32 rows (one pass of 256 threads)
                int r  = tid >> 3;
                int cs = tid & 7;
                uint32_t soff = r * SSTRIDE + cs * 16;
                const void* gb = g_A + (size_t)(col0 + r) * DIM + c * BK + cs * 8;
                cpasync16(sb + soff, gb);
            }
            asm volatile("cp.async.commit_group;" ::: "memory");
        };

        float acc[2][2][4];
        #pragma unroll
        for (int mt = 0; mt < 2; mt++)
            #pragma unroll
            for (int nt = 0; nt < 2; nt++)
                #pragma unroll
                for (int r = 0; r < 4; r++) acc[mt][nt][r] = 0.0f;

        const int wm  = (wid & 3) * 32;
        const int wn2 = (wid >> 2) * 16;    // 2 N-warps cover 32 cols
        const uint32_t a_base = (wm + (lane & 15)) * SSTRIDE + ((lane >> 4) * 16);
        const uint32_t b_base = (wn2 + (lane & 15)) * SSTRIDE + ((lane >> 4) * 16);

        issue_s(0, 0);

        #pragma unroll
        for (int c = 0; c < NCHUNK; c++) {
            int st = c & 1;
            if (c + 1 < NCHUNK) {
                issue_s(c + 1, st ^ 1);
                asm volatile("cp.async.wait_group 1;" ::: "memory");
            } else {
                asm volatile("cp.async.wait_group 0;" ::: "memory");
            }
            __syncthreads();

            uint32_t sa = sbase + st * 2 * STAGE_BYTES;
            uint32_t sb = sa + STAGE_BYTES;

            #pragma unroll
            for (int s = 0; s < 4; s++) {
                uint32_t a_frag[2][4];
                uint32_t b_reg[4];
                #pragma unroll
                for (int mt = 0; mt < 2; mt++)
                    LDSM_X4(a_frag[mt], sa + a_base + mt * (16 * SSTRIDE) + s * 32);
                LDSM_X4(b_reg, sb + b_base + s * 32);
                #pragma unroll
                for (int mt = 0; mt < 2; mt++) {
                    MMA16816(acc[mt][0], a_frag[mt], b_reg[0], b_reg[2]);
                    MMA16816(acc[mt][1], a_frag[mt], b_reg[1], b_reg[3]);
                }
            }
            __syncthreads();
        }

        const bool diagT = (bi == bj);   // parent-tile diagonal?
        wgt = ((row0 < N_PTS) ? 1.0f : -1.0f)
            * ((col0 < N_PTS) ? 1.0f : -1.0f)
            * (diagT ? 1.0f : 2.0f);

        #pragma unroll
        for (int mt = 0; mt < 2; mt++) {
            float ni0 = srm[wm + mt * 16 + (lane >> 2)];
            float ni1 = srm[wm + mt * 16 + (lane >> 2) + 8];
            #pragma unroll
            for (int nt = 0; nt < 2; nt++) {
                const int jc = wn2 + nt * 8 + (lane & 3) * 2;  // strip-local col
                float nj0 = srn[jc];
                float nj1 = srn[jc + 1];
                #pragma unroll
                for (int r = 0; r < 4; r++) {
                    float niv = (r >> 1) ? ni1 : ni0;
                    float njv = (r & 1) ? nj1 : nj0;
                    float d2 = niv + njv - 2.0f * acc[mt][nt][r];
                    if (d2 < 40.0f) {
                        int grow = row0 + wm + mt * 16 + (lane >> 2) + (r >> 1) * 8;
                        int gcol = col0 + jc + (r & 1);
                        if (grow != gcol)
                            local += __expf(-0.5f * fmaxf(d2, 0.0f));
                    }
                }
            }
        }
    }

    // Block reduction + global accumulate (shared by both paths)
    #pragma unroll
    for (int o = 16; o; o >>= 1) local += __shfl_xor_sync(0xffffffffu, local, o);
    if (lane == 0) red[wid] = local;
    __syncthreads();
    if (tid == 0) {
        float v = 0.0f;
        #pragma unroll
        for (int i = 0; i < 8; i++) v += red[i];
        atomicAdd(&g_accum, wgt * v);
        __threadfence();
        unsigned int tk = atomicAdd(&g_ticket, 1u);
        if (tk == GRIDT - 1) {
            float total = *((volatile float*)&g_accum);
            out[0] = (total + (float)NTOT) * (1.0f / ((float)N_PTS * (float)N_PTS));
        }
    }
}

extern "C" void kernel_launch(void* const* d_in, const int* in_sizes, int n_in,
                              void* d_out, int out_size) {
    const float* X = (const float*)d_in[0];
    const float* Y = (const float*)d_in[1];
    float* out = (float*)d_out;

    cudaFuncSetAttribute(mmd_mma_kernel,
                         cudaFuncAttributeMaxDynamicSharedMemorySize, SMEM_TOTAL);

    prep_kernel<<<NTOT / 32, 256>>>(X, Y);
    mmd_mma_kernel<<<GRIDT, 256, SMEM_TOTAL>>>(out);
}